// round 14
// baseline (speedup 1.0000x reference)
#include <cuda_runtime.h>
#include <cuda_fp16.h>
#include <math.h>
#include <stdint.h>

#define B_ROWS 16384
#define C_CLS  1000
#define F_DIM  256

// HMMA config (R12)
#define BM 128
#define BN 128
#define BK 32
#define NCHUNK (F_DIM / BK)
#define LDH 40
#define TILE_HALVES (128 * LDH)
#define BUF_HALVES  (2 * TILE_HALVES)
#define PARAM_OFF_H (2 * BUF_HALVES)
#define SMEM_BYTES  (PARAM_OFF_H * 2 + 2048)   // 83968 (covers FFMA needs too)

// row partition: rb%3<2 -> HMMA (86 blocks, 11008 rows), rb%3==2 -> FFMA (42 blocks)
#define HMMA_ROWS 11008

// FFMA config (R2)
#define FBK 16
#define FPAD 4

// ---- device scratch ----
__device__ __half g_fh[(size_t)B_ROWS * F_DIM];
__device__ __half g_mh[(size_t)C_CLS * F_DIM];
__device__ float g_scores[(size_t)B_ROWS * C_CLS];
__device__ float g_f2[B_ROWS];
__device__ float g_m2[C_CLS];

__device__ __forceinline__ uint32_t smem_u32(const void* p) {
    uint32_t a;
    asm("{ .reg .u64 t; cvta.to.shared.u64 t, %1; cvt.u32.u64 %0, t; }" : "=r"(a) : "l"(p));
    return a;
}
__device__ __forceinline__ void cp16(uint32_t daddr, const void* src, uint32_t bytes) {
    asm volatile("cp.async.ca.shared.global [%0], [%1], 16, %2;"
                 :: "r"(daddr), "l"(src), "r"(bytes) : "memory");
}
__device__ __forceinline__ void mma_f16(float* d, const uint32_t* a, const uint32_t* b) {
    asm volatile(
        "mma.sync.aligned.m16n8k16.row.col.f32.f16.f16.f32 "
        "{%0,%1,%2,%3}, {%4,%5,%6,%7}, {%8,%9}, {%0,%1,%2,%3};"
        : "+f"(d[0]), "+f"(d[1]), "+f"(d[2]), "+f"(d[3])
        : "r"(a[0]), "r"(a[1]), "r"(a[2]), "r"(a[3]), "r"(b[0]), "r"(b[1]));
}

// -------------------------------------------------------------------------
__global__ void convert_kernel(const float* __restrict__ x,
                               __half* __restrict__ xh_out,
                               float* __restrict__ sq, int rows) {
    int warp = (blockIdx.x * blockDim.x + threadIdx.x) >> 5;
    int lane = threadIdx.x & 31;
    if (warp >= rows) return;
    const float* xr = x + (size_t)warp * F_DIM;
    float s = 0.f;
#pragma unroll
    for (int i = 0; i < 2; i++) {
        int e = (lane + i * 32) * 4;
        float4 v = *(const float4*)(xr + e);
        s += v.x * v.x + v.y * v.y + v.z * v.z + v.w * v.w;
        __half2 h0 = __floats2half2_rn(v.x, v.y);
        __half2 h1 = __floats2half2_rn(v.z, v.w);
        uint2 u;
        u.x = *(uint32_t*)&h0;
        u.y = *(uint32_t*)&h1;
        *(uint2*)(xh_out + (size_t)warp * F_DIM + e) = u;
    }
#pragma unroll
    for (int o = 16; o; o >>= 1) s += __shfl_xor_sync(0xffffffffu, s, o);
    if (lane == 0) sq[warp] = s;
}

__device__ __forceinline__ float openmax_val(float dot, float lg, float f2v,
                                             float m2v, float sh, float lc,
                                             float isc) {
    float d2 = f2v + m2v - 2.f * dot;
    float dist = sqrtf(fmaxf(d2, 1e-12f));
    float xp = (dist - lc) * isc;
    float wv = 0.f;
    if (xp > 0.f) {
        float p = exp2f(sh * __log2f(xp));
        wv = 1.f - __expf(-p);
    }
    float w2 = wv * wv;
    float w4 = w2 * w2;
    float w10 = w4 * w4 * w2;
    return lg * (1.f - w10);
}

// -------------------------------------------------------------------------
// Mixed-kind GEMM: row-blocks rb%3<2 run the fp16 HMMA body (R12),
// rb%3==2 run the fp32 FFMA body (R2). Interleaved so every wave carries
// both kinds -> both the MMA unit and the fma pipe stay busy per SM.
// -------------------------------------------------------------------------
__global__ void __launch_bounds__(256, 2)
gemm_openmax_mixed(const float* __restrict__ featF,
                   const float* __restrict__ meanF,
                   const float* __restrict__ logits,
                   const float* __restrict__ wshape,
                   const float* __restrict__ wloc,
                   const float* __restrict__ wscale) {
    extern __shared__ __half smem[];
    const uint32_t sb = smem_u32(smem);
    const int tid = threadIdx.x;
    const int rb = blockIdx.y;
    const int colBase = blockIdx.x * BN;

    if (rb % 3 != 2) {
        // ================= HMMA path (R12 body) =================
        const int rowBase = (rb - rb / 3) * BM;
        const int lane = tid & 31;
        const int wid = tid >> 5;
        const int wm = wid & 1;
        const int wn = wid >> 1;

        float* m2s  = (float*)(smem + PARAM_OFF_H);
        float* shs  = m2s + 128;
        float* lcs  = shs + 128;
        float* iscs = lcs + 128;
        if (tid < 128) {
            int gc = colBase + tid;
            int cc = (gc < C_CLS) ? gc : 0;
            m2s[tid] = g_m2[cc];
            shs[tid] = wshape[cc];
            lcs[tid] = wloc[cc];
            iscs[tid] = 1.f / wscale[cc];
        }

        float acc[4][4][4];
#pragma unroll
        for (int i = 0; i < 4; i++)
#pragma unroll
            for (int j = 0; j < 4; j++)
#pragma unroll
                for (int q = 0; q < 4; q++) acc[i][j][q] = 0.f;

        auto loadChunk = [&](int ch, int buf) {
            const int k0 = ch * BK;
            const uint32_t sa = sb + (uint32_t)buf * BUF_HALVES * 2;
            const uint32_t sbB = sa + TILE_HALVES * 2;
#pragma unroll
            for (int it = 0; it < 2; it++) {
                int idx = tid + it * 256;
                int r = idx >> 2;
                int q8 = (idx & 3) * 8;
                const __half* gA = g_fh + (size_t)(rowBase + r) * F_DIM + k0 + q8;
                cp16(sa + (uint32_t)(r * LDH + q8) * 2, gA, 16u);
            }
#pragma unroll
            for (int it = 0; it < 2; it++) {
                int idx = tid + it * 256;
                int r = idx >> 2;
                int q8 = (idx & 3) * 8;
                int gc = colBase + r;
                const __half* gB = g_mh + (size_t)((gc < C_CLS) ? gc : 0) * F_DIM + k0 + q8;
                cp16(sbB + (uint32_t)(r * LDH + q8) * 2, gB, (gc < C_CLS) ? 16u : 0u);
            }
            asm volatile("cp.async.commit_group;" ::: "memory");
        };

        loadChunk(0, 0);

        const int g = lane >> 2;
        const int kq = lane & 3;
        const int lq = lane & 3;
        const int lr = lane >> 2;
        const int r0 = wm * 64 + g;
        const int c0 = wn * 32 + g;

#pragma unroll 1
        for (int ch = 0; ch < NCHUNK; ch++) {
            if (ch + 1 < NCHUNK) {
                loadChunk(ch + 1, (ch + 1) & 1);
                asm volatile("cp.async.wait_group 1;" ::: "memory");
            } else {
                asm volatile("cp.async.wait_group 0;" ::: "memory");
            }
            __syncthreads();

            const __half* A = smem + (ch & 1) * BUF_HALVES;
            const __half* Bs = A + TILE_HALVES;
#pragma unroll
            for (int ks = 0; ks < 2; ks++) {
                const int kb = ks * 16 + 2 * kq;
                uint32_t a[4][4], b[4][2];
#pragma unroll
                for (int ma = 0; ma < 4; ma++) {
                    const __half* ap = A + (r0 + ma * 16) * LDH + kb;
                    a[ma][0] = *(const uint32_t*)(ap);
                    a[ma][1] = *(const uint32_t*)(ap + 8 * LDH);
                    a[ma][2] = *(const uint32_t*)(ap + 8);
                    a[ma][3] = *(const uint32_t*)(ap + 8 * LDH + 8);
                }
#pragma unroll
                for (int na = 0; na < 4; na++) {
                    const __half* bp = Bs + (c0 + na * 8) * LDH + kb;
                    b[na][0] = *(const uint32_t*)(bp);
                    b[na][1] = *(const uint32_t*)(bp + 8);
                }
#pragma unroll
                for (int ma = 0; ma < 4; ma++)
#pragma unroll
                    for (int na = 0; na < 4; na++)
                        mma_f16(acc[ma][na], a[ma], b[na]);
            }
            __syncthreads();
        }

#pragma unroll
        for (int ma = 0; ma < 4; ma++) {
#pragma unroll
            for (int h = 0; h < 2; h++) {
                const int grow = rowBase + wm * 64 + ma * 16 + lr + h * 8;
                const float f2v = g_f2[grow];
                const float* lrow = logits + (size_t)grow * C_CLS;
                float* srow = g_scores + (size_t)grow * C_CLS;
#pragma unroll
                for (int na = 0; na < 4; na++) {
                    const int col = wn * 32 + na * 8 + 2 * lq;
                    const int gc = colBase + col;
                    if (gc >= C_CLS) continue;
                    float2 lg = *(const float2*)(lrow + gc);
                    float2 outp;
                    outp.x = openmax_val(acc[ma][na][h * 2], lg.x, f2v,
                                         m2s[col], shs[col], lcs[col], iscs[col]);
                    outp.y = openmax_val(acc[ma][na][h * 2 + 1], lg.y, f2v,
                                         m2s[col + 1], shs[col + 1], lcs[col + 1],
                                         iscs[col + 1]);
                    *(float2*)(srow + gc) = outp;
                }
            }
        }
    } else {
        // ================= FFMA path (R2 body) =================
        const int rowBase = HMMA_ROWS + (rb / 3) * BM;
        float* As = (float*)smem;                         // [FBK][BM+FPAD]
        float* Bs = As + FBK * (BM + FPAD);               // [FBK][BN+FPAD]

        const int tx = tid & 15;
        const int ty = tid >> 4;

        float acc[8][8];
#pragma unroll
        for (int i = 0; i < 8; i++)
#pragma unroll
            for (int j = 0; j < 8; j++) acc[i][j] = 0.f;

        for (int k0 = 0; k0 < F_DIM; k0 += FBK) {
#pragma unroll
            for (int l = 0; l < 2; l++) {
                int i = tid + l * 256;
                int r = i >> 2;
                int kc = (i & 3) * 4;
                float4 v = *(const float4*)(featF + (size_t)(rowBase + r) * F_DIM + k0 + kc);
                As[(kc + 0) * (BM + FPAD) + r] = v.x;
                As[(kc + 1) * (BM + FPAD) + r] = v.y;
                As[(kc + 2) * (BM + FPAD) + r] = v.z;
                As[(kc + 3) * (BM + FPAD) + r] = v.w;
            }
#pragma unroll
            for (int l = 0; l < 2; l++) {
                int i = tid + l * 256;
                int c = i >> 2;
                int kc = (i & 3) * 4;
                float4 v = make_float4(0.f, 0.f, 0.f, 0.f);
                int gc = colBase + c;
                if (gc < C_CLS)
                    v = *(const float4*)(meanF + (size_t)gc * F_DIM + k0 + kc);
                Bs[(kc + 0) * (BN + FPAD) + c] = v.x;
                Bs[(kc + 1) * (BN + FPAD) + c] = v.y;
                Bs[(kc + 2) * (BN + FPAD) + c] = v.z;
                Bs[(kc + 3) * (BN + FPAD) + c] = v.w;
            }
            __syncthreads();

#pragma unroll
            for (int kk = 0; kk < FBK; kk++) {
                float4 a0 = *(const float4*)&As[kk * (BM + FPAD) + ty * 8];
                float4 a1 = *(const float4*)&As[kk * (BM + FPAD) + ty * 8 + 4];
                float4 b0 = *(const float4*)&Bs[kk * (BN + FPAD) + tx * 8];
                float4 b1 = *(const float4*)&Bs[kk * (BN + FPAD) + tx * 8 + 4];
                float a[8] = {a0.x, a0.y, a0.z, a0.w, a1.x, a1.y, a1.z, a1.w};
                float b[8] = {b0.x, b0.y, b0.z, b0.w, b1.x, b1.y, b1.z, b1.w};
#pragma unroll
                for (int i = 0; i < 8; i++)
#pragma unroll
                    for (int j = 0; j < 8; j++)
                        acc[i][j] = fmaf(a[i], b[j], acc[i][j]);
            }
            __syncthreads();
        }

        // epilogue (params direct from global, R2-style)
        float m2v[8], shv[8], lcv[8], scv[8];
        int cidx[8];
#pragma unroll
        for (int j = 0; j < 8; j++) {
            int c = colBase + tx * 8 + j;
            cidx[j] = c;
            int cc = (c < C_CLS) ? c : 0;
            m2v[j] = g_m2[cc];
            shv[j] = wshape[cc];
            lcv[j] = wloc[cc];
            scv[j] = 1.f / wscale[cc];
        }
#pragma unroll
        for (int i = 0; i < 8; i++) {
            int row = rowBase + ty * 8 + i;
            const float f2v = g_f2[row];
            const float* lrow = logits + (size_t)row * C_CLS;
            float* srow = g_scores + (size_t)row * C_CLS;
#pragma unroll
            for (int j = 0; j < 8; j++) {
                if (cidx[j] >= C_CLS) continue;
                srow[cidx[j]] = openmax_val(acc[i][j], lrow[cidx[j]], f2v,
                                            m2v[j], shv[j], lcv[j], scv[j]);
            }
        }
    }
}

// -------------------------------------------------------------------------
// Row softmax over C=1000 (bounded scores -> no max pass).
// -------------------------------------------------------------------------
__global__ void __launch_bounds__(256)
softmax_kernel(const float* __restrict__ sc, float* __restrict__ out) {
    const int row = blockIdx.x;
    const int tid = threadIdx.x;
    const bool act = (tid < 250);

    float4 e = make_float4(0.f, 0.f, 0.f, 0.f);
    if (act) {
        float4 v = *(const float4*)(sc + (size_t)row * C_CLS + tid * 4);
        e.x = __expf(v.x);
        e.y = __expf(v.y);
        e.z = __expf(v.z);
        e.w = __expf(v.w);
    }
    float s = e.x + e.y + e.z + e.w;
#pragma unroll
    for (int o = 16; o; o >>= 1) s += __shfl_xor_sync(0xffffffffu, s, o);

    __shared__ float red[8];
    if ((tid & 31) == 0) red[tid >> 5] = s;
    __syncthreads();
    float total = red[0];
#pragma unroll
    for (int w = 1; w < 8; w++) total += red[w];
    const float inv = 1.f / total;

    if (act) {
        float4 o4;
        o4.x = e.x * inv;
        o4.y = e.y * inv;
        o4.z = e.z * inv;
        o4.w = e.w * inv;
        *(float4*)(out + (size_t)row * C_CLS + tid * 4) = o4;
    }
}

// -------------------------------------------------------------------------
extern "C" void kernel_launch(void* const* d_in, const int* in_sizes, int n_in,
                              void* d_out, int out_size) {
    const float* logits    = (const float*)d_in[0];
    const float* features  = (const float*)d_in[1];
    const float* mean_vecs = (const float*)d_in[2];
    const float* wb_shape  = (const float*)d_in[3];
    const float* wb_loc    = (const float*)d_in[4];
    const float* wb_scale  = (const float*)d_in[5];
    float* out = (float*)d_out;

    __half *fh, *mh;
    float *f2, *m2, *scores;
    cudaGetSymbolAddress((void**)&fh, g_fh);
    cudaGetSymbolAddress((void**)&mh, g_mh);
    cudaGetSymbolAddress((void**)&f2, g_f2);
    cudaGetSymbolAddress((void**)&m2, g_m2);
    cudaGetSymbolAddress((void**)&scores, g_scores);

    cudaFuncSetAttribute(gemm_openmax_mixed,
                         cudaFuncAttributeMaxDynamicSharedMemorySize, SMEM_BYTES);

    convert_kernel<<<B_ROWS / 8, 256>>>(features, fh, f2, B_ROWS);
    convert_kernel<<<(C_CLS + 7) / 8, 256>>>(mean_vecs, mh, m2, C_CLS);

    dim3 grid((C_CLS + BN - 1) / BN, 128);   // (8, 128): 86 HMMA + 42 FFMA row-blocks
    gemm_openmax_mixed<<<grid, 256, SMEM_BYTES>>>(features, mean_vecs, logits,
                                                  wb_shape, wb_loc, wb_scale);

    softmax_kernel<<<B_ROWS, 256>>>(scores, out);
    (void)in_sizes; (void)n_in; (void)out_size;
}

// round 15
// speedup vs baseline: 1.5701x; 1.5701x over previous
#include <cuda_runtime.h>
#include <cuda_fp16.h>
#include <math.h>
#include <stdint.h>

#define B_ROWS 16384
#define C_CLS  1000
#define F_DIM  256

#define BM 128
#define BN 128
#define BK 32                   // halves per K chunk
#define NCHUNK (F_DIM / BK)     // 8
#define LDH 40                  // smem row stride in halves (pad 8)
#define TILE_HALVES (128 * LDH)
#define BUF_HALVES  (2 * TILE_HALVES)
#define PARAM_OFF_H (2 * BUF_HALVES)
#define SMEM_BYTES  (PARAM_OFF_H * 2 + 2048)

// ---- device scratch ----
__device__ __half g_fh[(size_t)B_ROWS * F_DIM];     // fp16 features
__device__ __half g_mh[(size_t)C_CLS * F_DIM];      // fp16 mean_vecs
__device__ __half g_escores[(size_t)B_ROWS * C_CLS];// fp16 exp(score)
__device__ float g_f2[B_ROWS];
__device__ float g_m2[C_CLS];

__device__ __forceinline__ uint32_t smem_u32(const void* p) {
    uint32_t a;
    asm("{ .reg .u64 t; cvta.to.shared.u64 t, %1; cvt.u32.u64 %0, t; }" : "=r"(a) : "l"(p));
    return a;
}
__device__ __forceinline__ void cp16(uint32_t daddr, const void* src, uint32_t bytes) {
    asm volatile("cp.async.ca.shared.global [%0], [%1], 16, %2;"
                 :: "r"(daddr), "l"(src), "r"(bytes) : "memory");
}
__device__ __forceinline__ void mma_f16(float* d, const uint32_t* a, const uint32_t* b) {
    asm volatile(
        "mma.sync.aligned.m16n8k16.row.col.f32.f16.f16.f32 "
        "{%0,%1,%2,%3}, {%4,%5,%6,%7}, {%8,%9}, {%0,%1,%2,%3};"
        : "+f"(d[0]), "+f"(d[1]), "+f"(d[2]), "+f"(d[3])
        : "r"(a[0]), "r"(a[1]), "r"(a[2]), "r"(a[3]), "r"(b[0]), "r"(b[1]));
}

// -------------------------------------------------------------------------
// Merged convert: warps [0, B_ROWS) -> features, [B_ROWS, B_ROWS+C_CLS) ->
// mean_vecs. fp32 -> fp16 + row sum-of-squares. One warp per row.
// -------------------------------------------------------------------------
__global__ void convert_kernel(const float* __restrict__ feat,
                               const float* __restrict__ mean) {
    int warp = (blockIdx.x * blockDim.x + threadIdx.x) >> 5;
    int lane = threadIdx.x & 31;
    if (warp >= B_ROWS + C_CLS) return;
    const bool isF = (warp < B_ROWS);
    const int row = isF ? warp : (warp - B_ROWS);
    const float* xr = (isF ? feat : mean) + (size_t)row * F_DIM;
    __half* dst = (isF ? g_fh : g_mh) + (size_t)row * F_DIM;
    float s = 0.f;
#pragma unroll
    for (int i = 0; i < 2; i++) {
        int e = (lane + i * 32) * 4;
        float4 v = *(const float4*)(xr + e);
        s += v.x * v.x + v.y * v.y + v.z * v.z + v.w * v.w;
        __half2 h0 = __floats2half2_rn(v.x, v.y);
        __half2 h1 = __floats2half2_rn(v.z, v.w);
        uint2 u;
        u.x = *(uint32_t*)&h0;
        u.y = *(uint32_t*)&h1;
        *(uint2*)(dst + e) = u;
    }
#pragma unroll
    for (int o = 16; o; o >>= 1) s += __shfl_xor_sync(0xffffffffu, s, o);
    if (lane == 0) {
        if (isF) g_f2[row] = s; else g_m2[row] = s;
    }
}

// -------------------------------------------------------------------------
// fp16 mma.sync GEMM + OpenMax epilogue writing exp(score) as fp16.
// (R12 GEMM core, unchanged except the epilogue store.)
// -------------------------------------------------------------------------
__global__ void __launch_bounds__(256, 2)
gemm_openmax_tc(const float* __restrict__ logits,
                const float* __restrict__ wshape,
                const float* __restrict__ wloc,
                const float* __restrict__ wscale) {
    extern __shared__ __half smem[];
    const uint32_t sb = smem_u32(smem);
    const int tid = threadIdx.x;
    const int lane = tid & 31;
    const int wid = tid >> 5;
    const int wm = wid & 1;
    const int wn = wid >> 1;
    const int rowBase = blockIdx.y * BM;
    const int colBase = blockIdx.x * BN;

    float* m2s  = (float*)(smem + PARAM_OFF_H);
    float* shs  = m2s + 128;
    float* lcs  = shs + 128;
    float* iscs = lcs + 128;
    if (tid < 128) {
        int gc = colBase + tid;
        int cc = (gc < C_CLS) ? gc : 0;
        m2s[tid] = g_m2[cc];
        shs[tid] = wshape[cc];
        lcs[tid] = wloc[cc];
        iscs[tid] = 1.f / wscale[cc];
    }

    float acc[4][4][4];
#pragma unroll
    for (int i = 0; i < 4; i++)
#pragma unroll
        for (int j = 0; j < 4; j++)
#pragma unroll
            for (int q = 0; q < 4; q++) acc[i][j][q] = 0.f;

    auto loadChunk = [&](int ch, int buf) {
        const int k0 = ch * BK;
        const uint32_t sa = sb + (uint32_t)buf * BUF_HALVES * 2;
        const uint32_t sbB = sa + TILE_HALVES * 2;
#pragma unroll
        for (int it = 0; it < 2; it++) {
            int idx = tid + it * 256;
            int r = idx >> 2;
            int q8 = (idx & 3) * 8;
            const __half* gA = g_fh + (size_t)(rowBase + r) * F_DIM + k0 + q8;
            cp16(sa + (uint32_t)(r * LDH + q8) * 2, gA, 16u);
        }
#pragma unroll
        for (int it = 0; it < 2; it++) {
            int idx = tid + it * 256;
            int r = idx >> 2;
            int q8 = (idx & 3) * 8;
            int gc = colBase + r;
            const __half* gB = g_mh + (size_t)((gc < C_CLS) ? gc : 0) * F_DIM + k0 + q8;
            cp16(sbB + (uint32_t)(r * LDH + q8) * 2, gB, (gc < C_CLS) ? 16u : 0u);
        }
        asm volatile("cp.async.commit_group;" ::: "memory");
    };

    loadChunk(0, 0);

    const int g = lane >> 2;
    const int kq = lane & 3;
    const int lq = lane & 3;
    const int lr = lane >> 2;
    const int r0 = wm * 64 + g;
    const int c0 = wn * 32 + g;

#pragma unroll 1
    for (int ch = 0; ch < NCHUNK; ch++) {
        if (ch + 1 < NCHUNK) {
            loadChunk(ch + 1, (ch + 1) & 1);
            asm volatile("cp.async.wait_group 1;" ::: "memory");
        } else {
            asm volatile("cp.async.wait_group 0;" ::: "memory");
        }
        __syncthreads();

        const __half* A = smem + (ch & 1) * BUF_HALVES;
        const __half* Bs = A + TILE_HALVES;
#pragma unroll
        for (int ks = 0; ks < 2; ks++) {
            const int kb = ks * 16 + 2 * kq;
            uint32_t a[4][4], b[4][2];
#pragma unroll
            for (int ma = 0; ma < 4; ma++) {
                const __half* ap = A + (r0 + ma * 16) * LDH + kb;
                a[ma][0] = *(const uint32_t*)(ap);
                a[ma][1] = *(const uint32_t*)(ap + 8 * LDH);
                a[ma][2] = *(const uint32_t*)(ap + 8);
                a[ma][3] = *(const uint32_t*)(ap + 8 * LDH + 8);
            }
#pragma unroll
            for (int na = 0; na < 4; na++) {
                const __half* bp = Bs + (c0 + na * 8) * LDH + kb;
                b[na][0] = *(const uint32_t*)(bp);
                b[na][1] = *(const uint32_t*)(bp + 8);
            }
#pragma unroll
            for (int ma = 0; ma < 4; ma++)
#pragma unroll
                for (int na = 0; na < 4; na++)
                    mma_f16(acc[ma][na], a[ma], b[na]);
        }
        __syncthreads();
    }

    // ---- fused OpenMax epilogue: store exp(score) as fp16 ----
#pragma unroll
    for (int ma = 0; ma < 4; ma++) {
#pragma unroll
        for (int h = 0; h < 2; h++) {
            const int grow = rowBase + wm * 64 + ma * 16 + lr + h * 8;
            const float f2v = g_f2[grow];
            const float* lrow = logits + (size_t)grow * C_CLS;
            __half* erow = g_escores + (size_t)grow * C_CLS;
#pragma unroll
            for (int na = 0; na < 4; na++) {
                const int col = wn * 32 + na * 8 + 2 * lq;
                const int gc = colBase + col;
                if (gc >= C_CLS) continue;
                float2 lg = *(const float2*)(lrow + gc);
                float dots[2] = { acc[ma][na][h * 2], acc[ma][na][h * 2 + 1] };
                float lgv[2] = { lg.x, lg.y };
                float res[2];
#pragma unroll
                for (int q = 0; q < 2; q++) {
                    const int c = col + q;
                    float d2 = f2v + m2s[c] - 2.f * dots[q];
                    float dist = sqrtf(fmaxf(d2, 1e-12f));
                    float xp = (dist - lcs[c]) * iscs[c];
                    float wv = 0.f;
                    if (xp > 0.f) {
                        float p = exp2f(shs[c] * __log2f(xp));
                        wv = 1.f - __expf(-p);
                    }
                    float w2 = wv * wv;
                    float w4 = w2 * w2;
                    float w10 = w4 * w4 * w2;
                    res[q] = __expf(lgv[q] * (1.f - w10));
                }
                __half2 eh = __floats2half2_rn(res[0], res[1]);
                *(__half2*)(erow + gc) = eh;
            }
        }
    }
}

// -------------------------------------------------------------------------
// Softmax scale v3: e already exponentiated (fp16). 2 rows per 256-thread
// block; 125 threads/row, each owns 8 halves (uint4 load) -> 8 fp32 out.
// -------------------------------------------------------------------------
__global__ void __launch_bounds__(256)
softmax_kernel(float* __restrict__ out) {
    const int tid = threadIdx.x;
    const int half_id = tid >> 7;              // 0 or 1
    const int t = tid & 127;                   // 0..127
    const int row = blockIdx.x * 2 + half_id;
    const bool act = (t < 125);

    float v[8];
    float s = 0.f;
    if (act) {
        uint4 u = *(const uint4*)(g_escores + (size_t)row * C_CLS + t * 8);
        const __half2* hp = (const __half2*)&u;
#pragma unroll
        for (int i = 0; i < 4; i++) {
            float2 f = __half22float2(hp[i]);
            v[i * 2] = f.x;
            v[i * 2 + 1] = f.y;
            s += f.x + f.y;
        }
    } else {
#pragma unroll
        for (int i = 0; i < 8; i++) v[i] = 0.f;
    }
#pragma unroll
    for (int o = 16; o; o >>= 1) s += __shfl_xor_sync(0xffffffffu, s, o);

    __shared__ float red[8];
    if ((tid & 31) == 0) red[tid >> 5] = s;
    __syncthreads();
    float total = 0.f;
#pragma unroll
    for (int w = 0; w < 4; w++) total += red[half_id * 4 + w];
    const float inv = 1.f / total;

    if (act) {
        float* orow = out + (size_t)row * C_CLS + t * 8;
        float4 o0, o1;
        o0.x = v[0] * inv; o0.y = v[1] * inv; o0.z = v[2] * inv; o0.w = v[3] * inv;
        o1.x = v[4] * inv; o1.y = v[5] * inv; o1.z = v[6] * inv; o1.w = v[7] * inv;
        *(float4*)(orow) = o0;
        *(float4*)(orow + 4) = o1;
    }
}

// -------------------------------------------------------------------------
extern "C" void kernel_launch(void* const* d_in, const int* in_sizes, int n_in,
                              void* d_out, int out_size) {
    const float* logits    = (const float*)d_in[0];
    const float* features  = (const float*)d_in[1];
    const float* mean_vecs = (const float*)d_in[2];
    const float* wb_shape  = (const float*)d_in[3];
    const float* wb_loc    = (const float*)d_in[4];
    const float* wb_scale  = (const float*)d_in[5];
    float* out = (float*)d_out;

    cudaFuncSetAttribute(gemm_openmax_tc,
                         cudaFuncAttributeMaxDynamicSharedMemorySize, SMEM_BYTES);

    // merged converts: 16384 + 1000 rows, 8 warps/block
    convert_kernel<<<(B_ROWS + C_CLS + 7) / 8, 256>>>(features, mean_vecs);

    dim3 grid((C_CLS + BN - 1) / BN, B_ROWS / BM);   // (8, 128)
    gemm_openmax_tc<<<grid, 256, SMEM_BYTES>>>(logits, wb_shape, wb_loc, wb_scale);

    softmax_kernel<<<B_ROWS / 2, 256>>>(out);
    (void)in_sizes; (void)n_in; (void)out_size;
}

// round 16
// speedup vs baseline: 1.5921x; 1.0140x over previous
#include <cuda_runtime.h>
#include <cuda_fp16.h>
#include <math.h>
#include <stdint.h>

#define B_ROWS 16384
#define C_CLS  1000
#define F_DIM  256

#define BM 128
#define BN 128
#define BK 32                   // halves per K chunk
#define NCHUNK (F_DIM / BK)     // 8
#define LDH 40                  // smem row stride in halves (pad 8)
#define TILE_HALVES (128 * LDH)
#define BUF_HALVES  (2 * TILE_HALVES)
#define PARAM_OFF_H (2 * BUF_HALVES)
#define SMEM_BYTES  (PARAM_OFF_H * 2 + 2048)

// ---- device scratch ----
__device__ __half g_fh[(size_t)B_ROWS * F_DIM];     // fp16 features
__device__ __half g_mh[(size_t)C_CLS * F_DIM];      // fp16 mean_vecs
__device__ __half g_escores[(size_t)B_ROWS * C_CLS];// fp16 exp(score)
__device__ float g_f2[B_ROWS];
__device__ float g_m2[C_CLS];

__device__ __forceinline__ uint32_t smem_u32(const void* p) {
    uint32_t a;
    asm("{ .reg .u64 t; cvta.to.shared.u64 t, %1; cvt.u32.u64 %0, t; }" : "=r"(a) : "l"(p));
    return a;
}
__device__ __forceinline__ void cp16(uint32_t daddr, const void* src, uint32_t bytes) {
    asm volatile("cp.async.ca.shared.global [%0], [%1], 16, %2;"
                 :: "r"(daddr), "l"(src), "r"(bytes) : "memory");
}
__device__ __forceinline__ void mma_f16(float* d, const uint32_t* a, const uint32_t* b) {
    asm volatile(
        "mma.sync.aligned.m16n8k16.row.col.f32.f16.f16.f32 "
        "{%0,%1,%2,%3}, {%4,%5,%6,%7}, {%8,%9}, {%0,%1,%2,%3};"
        : "+f"(d[0]), "+f"(d[1]), "+f"(d[2]), "+f"(d[3])
        : "r"(a[0]), "r"(a[1]), "r"(a[2]), "r"(a[3]), "r"(b[0]), "r"(b[1]));
}

// -------------------------------------------------------------------------
// Convert v2: 2 rows per warp, 4 float4 loads front-batched (MLP=4/thread),
// interleaved shuffle reductions. Rows [0,B_ROWS) = features,
// [B_ROWS, B_ROWS+C_CLS) = mean_vecs.
// -------------------------------------------------------------------------
__global__ void convert_kernel(const float* __restrict__ feat,
                               const float* __restrict__ mean) {
    const int warp = (blockIdx.x * blockDim.x + threadIdx.x) >> 5;
    const int lane = threadIdx.x & 31;
    const int nrows = B_ROWS + C_CLS;

    float4 v[4];
    const float* src[2];
    __half* dst[2];
    int rowid[2];
    bool isF[2];
#pragma unroll
    for (int r = 0; r < 2; r++) {
        int grow = warp * 2 + r;
        bool ok = (grow < nrows);
        int gr = ok ? grow : 0;
        isF[r] = (gr < B_ROWS);
        rowid[r] = isF[r] ? gr : (gr - B_ROWS);
        src[r] = (isF[r] ? feat : mean) + (size_t)rowid[r] * F_DIM;
        dst[r] = (isF[r] ? g_fh : g_mh) + (size_t)rowid[r] * F_DIM;
        if (!ok) src[r] = nullptr;
    }
    if (warp * 2 >= nrows) return;

    // front-batched loads: 4 independent float4 per thread
#pragma unroll
    for (int r = 0; r < 2; r++)
#pragma unroll
        for (int i = 0; i < 2; i++)
            v[r * 2 + i] = src[r] ? *(const float4*)(src[r] + (lane + i * 32) * 4)
                                  : make_float4(0.f, 0.f, 0.f, 0.f);

    float s[2] = {0.f, 0.f};
#pragma unroll
    for (int r = 0; r < 2; r++) {
        if (!src[r]) continue;
#pragma unroll
        for (int i = 0; i < 2; i++) {
            float4 w = v[r * 2 + i];
            s[r] += w.x * w.x + w.y * w.y + w.z * w.z + w.w * w.w;
            __half2 h0 = __floats2half2_rn(w.x, w.y);
            __half2 h1 = __floats2half2_rn(w.z, w.w);
            uint2 u;
            u.x = *(uint32_t*)&h0;
            u.y = *(uint32_t*)&h1;
            *(uint2*)(dst[r] + (lane + i * 32) * 4) = u;
        }
    }
    // interleaved independent reductions
#pragma unroll
    for (int o = 16; o; o >>= 1) {
        s[0] += __shfl_xor_sync(0xffffffffu, s[0], o);
        s[1] += __shfl_xor_sync(0xffffffffu, s[1], o);
    }
    if (lane == 0) {
#pragma unroll
        for (int r = 0; r < 2; r++) {
            if (!src[r]) continue;
            if (isF[r]) g_f2[rowid[r]] = s[r];
            else        g_m2[rowid[r]] = s[r];
        }
    }
}

// -------------------------------------------------------------------------
// fp16 mma.sync GEMM + OpenMax epilogue writing exp(score) as fp16.
// (R15 kernel, unchanged.)
// -------------------------------------------------------------------------
__global__ void __launch_bounds__(256, 2)
gemm_openmax_tc(const float* __restrict__ logits,
                const float* __restrict__ wshape,
                const float* __restrict__ wloc,
                const float* __restrict__ wscale) {
    extern __shared__ __half smem[];
    const uint32_t sb = smem_u32(smem);
    const int tid = threadIdx.x;
    const int lane = tid & 31;
    const int wid = tid >> 5;
    const int wm = wid & 1;
    const int wn = wid >> 1;
    const int rowBase = blockIdx.y * BM;
    const int colBase = blockIdx.x * BN;

    float* m2s  = (float*)(smem + PARAM_OFF_H);
    float* shs  = m2s + 128;
    float* lcs  = shs + 128;
    float* iscs = lcs + 128;
    if (tid < 128) {
        int gc = colBase + tid;
        int cc = (gc < C_CLS) ? gc : 0;
        m2s[tid] = g_m2[cc];
        shs[tid] = wshape[cc];
        lcs[tid] = wloc[cc];
        iscs[tid] = 1.f / wscale[cc];
    }

    float acc[4][4][4];
#pragma unroll
    for (int i = 0; i < 4; i++)
#pragma unroll
        for (int j = 0; j < 4; j++)
#pragma unroll
            for (int q = 0; q < 4; q++) acc[i][j][q] = 0.f;

    auto loadChunk = [&](int ch, int buf) {
        const int k0 = ch * BK;
        const uint32_t sa = sb + (uint32_t)buf * BUF_HALVES * 2;
        const uint32_t sbB = sa + TILE_HALVES * 2;
#pragma unroll
        for (int it = 0; it < 2; it++) {
            int idx = tid + it * 256;
            int r = idx >> 2;
            int q8 = (idx & 3) * 8;
            const __half* gA = g_fh + (size_t)(rowBase + r) * F_DIM + k0 + q8;
            cp16(sa + (uint32_t)(r * LDH + q8) * 2, gA, 16u);
        }
#pragma unroll
        for (int it = 0; it < 2; it++) {
            int idx = tid + it * 256;
            int r = idx >> 2;
            int q8 = (idx & 3) * 8;
            int gc = colBase + r;
            const __half* gB = g_mh + (size_t)((gc < C_CLS) ? gc : 0) * F_DIM + k0 + q8;
            cp16(sbB + (uint32_t)(r * LDH + q8) * 2, gB, (gc < C_CLS) ? 16u : 0u);
        }
        asm volatile("cp.async.commit_group;" ::: "memory");
    };

    loadChunk(0, 0);

    const int g = lane >> 2;
    const int kq = lane & 3;
    const int lq = lane & 3;
    const int lr = lane >> 2;
    const int r0 = wm * 64 + g;
    const int c0 = wn * 32 + g;

#pragma unroll 1
    for (int ch = 0; ch < NCHUNK; ch++) {
        if (ch + 1 < NCHUNK) {
            loadChunk(ch + 1, (ch + 1) & 1);
            asm volatile("cp.async.wait_group 1;" ::: "memory");
        } else {
            asm volatile("cp.async.wait_group 0;" ::: "memory");
        }
        __syncthreads();

        const __half* A = smem + (ch & 1) * BUF_HALVES;
        const __half* Bs = A + TILE_HALVES;
#pragma unroll
        for (int ks = 0; ks < 2; ks++) {
            const int kb = ks * 16 + 2 * kq;
            uint32_t a[4][4], b[4][2];
#pragma unroll
            for (int ma = 0; ma < 4; ma++) {
                const __half* ap = A + (r0 + ma * 16) * LDH + kb;
                a[ma][0] = *(const uint32_t*)(ap);
                a[ma][1] = *(const uint32_t*)(ap + 8 * LDH);
                a[ma][2] = *(const uint32_t*)(ap + 8);
                a[ma][3] = *(const uint32_t*)(ap + 8 * LDH + 8);
            }
#pragma unroll
            for (int na = 0; na < 4; na++) {
                const __half* bp = Bs + (c0 + na * 8) * LDH + kb;
                b[na][0] = *(const uint32_t*)(bp);
                b[na][1] = *(const uint32_t*)(bp + 8);
            }
#pragma unroll
            for (int ma = 0; ma < 4; ma++)
#pragma unroll
                for (int na = 0; na < 4; na++)
                    mma_f16(acc[ma][na], a[ma], b[na]);
        }
        __syncthreads();
    }

    // ---- fused OpenMax epilogue: store exp(score) as fp16 ----
#pragma unroll
    for (int ma = 0; ma < 4; ma++) {
#pragma unroll
        for (int h = 0; h < 2; h++) {
            const int grow = rowBase + wm * 64 + ma * 16 + lr + h * 8;
            const float f2v = g_f2[grow];
            const float* lrow = logits + (size_t)grow * C_CLS;
            __half* erow = g_escores + (size_t)grow * C_CLS;
#pragma unroll
            for (int na = 0; na < 4; na++) {
                const int col = wn * 32 + na * 8 + 2 * lq;
                const int gc = colBase + col;
                if (gc >= C_CLS) continue;
                float2 lg = *(const float2*)(lrow + gc);
                float dots[2] = { acc[ma][na][h * 2], acc[ma][na][h * 2 + 1] };
                float lgv[2] = { lg.x, lg.y };
                float res[2];
#pragma unroll
                for (int q = 0; q < 2; q++) {
                    const int c = col + q;
                    float d2 = f2v + m2s[c] - 2.f * dots[q];
                    float dist = sqrtf(fmaxf(d2, 1e-12f));
                    float xp = (dist - lcs[c]) * iscs[c];
                    float wv = 0.f;
                    if (xp > 0.f) {
                        float p = exp2f(shs[c] * __log2f(xp));
                        wv = 1.f - __expf(-p);
                    }
                    float w2 = wv * wv;
                    float w4 = w2 * w2;
                    float w10 = w4 * w4 * w2;
                    res[q] = __expf(lgv[q] * (1.f - w10));
                }
                __half2 eh = __floats2half2_rn(res[0], res[1]);
                *(__half2*)(erow + gc) = eh;
            }
        }
    }
}

// -------------------------------------------------------------------------
// Softmax scale: e already exponentiated (fp16). 2 rows / 256-thread block.
// -------------------------------------------------------------------------
__global__ void __launch_bounds__(256)
softmax_kernel(float* __restrict__ out) {
    const int tid = threadIdx.x;
    const int half_id = tid >> 7;
    const int t = tid & 127;
    const int row = blockIdx.x * 2 + half_id;
    const bool act = (t < 125);

    float v[8];
    float s = 0.f;
    if (act) {
        uint4 u = *(const uint4*)(g_escores + (size_t)row * C_CLS + t * 8);
        const __half2* hp = (const __half2*)&u;
#pragma unroll
        for (int i = 0; i < 4; i++) {
            float2 f = __half22float2(hp[i]);
            v[i * 2] = f.x;
            v[i * 2 + 1] = f.y;
            s += f.x + f.y;
        }
    } else {
#pragma unroll
        for (int i = 0; i < 8; i++) v[i] = 0.f;
    }
#pragma unroll
    for (int o = 16; o; o >>= 1) s += __shfl_xor_sync(0xffffffffu, s, o);

    __shared__ float red[8];
    if ((tid & 31) == 0) red[tid >> 5] = s;
    __syncthreads();
    float total = 0.f;
#pragma unroll
    for (int w = 0; w < 4; w++) total += red[half_id * 4 + w];
    const float inv = 1.f / total;

    if (act) {
        float* orow = out + (size_t)row * C_CLS + t * 8;
        float4 o0, o1;
        o0.x = v[0] * inv; o0.y = v[1] * inv; o0.z = v[2] * inv; o0.w = v[3] * inv;
        o1.x = v[4] * inv; o1.y = v[5] * inv; o1.z = v[6] * inv; o1.w = v[7] * inv;
        *(float4*)(orow) = o0;
        *(float4*)(orow + 4) = o1;
    }
}

// -------------------------------------------------------------------------
extern "C" void kernel_launch(void* const* d_in, const int* in_sizes, int n_in,
                              void* d_out, int out_size) {
    const float* logits    = (const float*)d_in[0];
    const float* features  = (const float*)d_in[1];
    const float* mean_vecs = (const float*)d_in[2];
    const float* wb_shape  = (const float*)d_in[3];
    const float* wb_loc    = (const float*)d_in[4];
    const float* wb_scale  = (const float*)d_in[5];
    float* out = (float*)d_out;

    cudaFuncSetAttribute(gemm_openmax_tc,
                         cudaFuncAttributeMaxDynamicSharedMemorySize, SMEM_BYTES);

    // convert v2: 2 rows/warp -> 16 rows/block; (16384+1000)/16 -> 1087 blocks
    convert_kernel<<<(B_ROWS + C_CLS + 15) / 16, 256>>>(features, mean_vecs);

    dim3 grid((C_CLS + BN - 1) / BN, B_ROWS / BM);   // (8, 128)
    gemm_openmax_tc<<<grid, 256, SMEM_BYTES>>>(logits, wb_shape, wb_loc, wb_scale);

    softmax_kernel<<<B_ROWS / 2, 256>>>(out);
    (void)in_sizes; (void)n_in; (void)out_size;
}